// round 14
// baseline (speedup 1.0000x reference)
#include <cuda_runtime.h>
#include <cstddef>
#include <cstdint>

// CTC loss forward. B=32, T=800, C=5000, L=100, S=201.
//
// R13 = R12 (merged alpha+gather kernel, flag-paced overlap) + SM ISOLATION:
// ~140KB of unused dynamic smem per block forces 1 block/SM, so gather CTAs
// can never co-reside with (and L1tex-poison) the 32 alpha CTAs. R12's
// regression (133.6us, occ 28.7%) was exactly this co-residency: ~7 gather
// blocks per alpha SM dumped ~700 scattered wavefronts each into the alpha
// SM's L1tex queue. Gather now runs 1 block/SM on the other 116 SMs
// (243MB @ LTS cap ~ 25-40us, fully hidden under the 82.6us recursion).

#define Bb 32
#define Tt 800
#define Cc 5000
#define Ll 100
#define EP 128            // emit row stride (floats), line-aligned
#define NEGV (-1e30f)
#define LOG2E 1.4426950408889634f
#define LN2   0.6931471805599453f
#define DP 4              // prefetch depth in PAIRS (8 time steps)
#define NTHR 128
#define CH 8              // rows per gather chunk
#define NCHUNK (Tt / CH)  // 100
#define NGATHER (NCHUNK * Bb)
#define SMEM_DYN (140 * 1024)   // forces 1 block/SM (2*140KB > 228KB)

__device__ float    g_emit[(size_t)Bb * Tt * EP];
__device__ float    g_tot[Bb];
__device__ unsigned g_done;              // self-resetting
__device__ int      g_flag[NGATHER];     // reset each replay by reset_kernel

__device__ __forceinline__ float ex2f(float x) {
    float y; asm("ex2.approx.ftz.f32 %0, %1;" : "=f"(y) : "f"(x)); return y;
}
__device__ __forceinline__ float lg2f(float x) {
    float y; asm("lg2.approx.ftz.f32 %0, %1;" : "=f"(y) : "f"(x)); return y;
}
__device__ __forceinline__ int ld_acq(const int* p) {
    int v;
    asm volatile("ld.acquire.gpu.global.b32 %0, [%1];"
                 : "=r"(v) : "l"(p) : "memory");
    return v;
}
__device__ __forceinline__ void st_rel(int* p, int v) {
    asm volatile("st.release.gpu.global.b32 [%0], %1;"
                 :: "l"(p), "r"(v) : "memory");
}

// (base,sum) logaddexp combine: (bx,sx) (+) (by,sy) -> (mb, ms), single ex2.
#define LAE(bx, sx, by, sy, mb, ms)                                        \
    {                                                                      \
        float d_ = __fadd_rn(bx, -(by));                                   \
        float u_ = ex2f(fminf(d_, -d_));                                   \
        mb = fmaxf(bx, by);                                                \
        ms = (d_ >= 0.f) ? __fmaf_rn(sy, u_, sx) : __fmaf_rn(sx, u_, sy);  \
    }

// ---------------------------------------------------------------------------
__global__ void reset_kernel() {
    int i = blockIdx.x * blockDim.x + threadIdx.x;
    if (i < NGATHER) g_flag[i] = 0;
}

// ---------------------------------------------------------------------------
// Merged kernel. bid < Bb: alpha block for batch bid. bid >= Bb: gather.
// ---------------------------------------------------------------------------
__global__ __launch_bounds__(NTHR, 1)
void ctc_main(const float* __restrict__ lp,
              const int* __restrict__ targets,
              const int* __restrict__ ilen,
              const int* __restrict__ tlen,
              float* __restrict__ out)
{
    extern __shared__ char _smem_pad[];  // unused; occupancy limiter

    // ======================= GATHER BLOCKS =======================
    if (blockIdx.x >= Bb) {
        const int g  = blockIdx.x - Bb;
        const int ct = g >> 5;           // chunk (t/8), chunk-major order
        const int b  = g & 31;
        const int il = ilen[b];
        const int r0 = ct * CH;
        const float* __restrict__ rowp = lp + (size_t)b * Tt * Cc;
        for (int idx = threadIdx.x; idx < CH * (Ll + 1); idx += NTHR) {
            int dr = idx / (Ll + 1);
            int j  = idx - dr * (Ll + 1);
            int r  = r0 + dr;
            if (r < il) {
                int c = (j == 0) ? 0 : targets[b * Ll + (j - 1)];
                g_emit[(size_t)(b * Tt + r) * EP + j] =
                    LOG2E * __ldg(rowp + (size_t)r * Cc + c);
            }
        }
        __syncthreads();
        if (threadIdx.x == 0) st_rel(&g_flag[ct * Bb + b], 1);
        return;
    }

    // ======================= ALPHA BLOCKS ========================
    __shared__ float4 sh[2][NTHR + 2];
    __shared__ int s_lastflag;

    const int b = blockIdx.x;
    const int i = threadIdx.x;
    const int last = ilen[b] - 1;

    const int tgR   = (i < Ll)              ? targets[b * Ll + i]     : 0;
    const int tgpR  = (i >= 1 && i <= Ll)   ? targets[b * Ll + i - 1] : -1;
    const int tgppR = (i >= 2 && i <= Ll+1) ? targets[b * Ll + i - 2] : -1;
    const bool skip  = (tgR  != tgpR);
    const bool skipP = (tgpR != tgppR);
    const int jo = (i < Ll)            ? i + 1 : 0;   // own odd emission col
    const int jp = (i >= 1 && i <= Ll) ? i     : 0;   // neighbor odd col

    const float* __restrict__ em = g_emit + (size_t)b * Tt * EP;

    if (i < 2) {
        sh[0][i] = make_float4(NEGV, 0.f, NEGV, 0.f);
        sh[1][i] = make_float4(NEGV, 0.f, NEGV, 0.f);
    }

    const int ts0  = (last & 1) ? 1 : 0;
    const int maxc = last >> 3;                  // last chunk alpha reads
    // Pre-wait chunks covering rows 0 .. ts0+16 (init + rings + group 0).
    int wc = (ts0 + 16) >> 3; if (wc > maxc) wc = maxc;
    for (int c = 0; c <= wc; ++c)
        while (ld_acq(&g_flag[c * Bb + b]) == 0) {}
    int nextc = wc;                              // highest ensured chunk
    int pfc = (nextc < maxc) ? nextc + 1 : -1;   // pipelined flag chunk
    int pfv = (pfc >= 0) ? ld_acq(&g_flag[pfc * Bb + b]) : 1;

    // t=0 init (log2 domain, alpha = base + lg2(sum)); emit pre-scaled.
    float se = 1.f, so = 1.f;
    float be = (i == 0) ? em[0]  : NEGV;
    float bo = (i == 0) ? em[jo] : NEGV;

    int buf = 0;
    sh[buf][i + 2] = make_float4(be, se, bo, so);
    __syncthreads();

#define PAIR_BODY(e1b, e1o, e1p, e2b, e2o)                                   \
    {                                                                        \
        float4 n1 = sh[buf][i + 1];                                          \
        float4 n2 = sh[buf][i];                                              \
        float mR1, sR1; LAE(n1.z, n1.w, n1.x, n1.y, mR1, sR1);               \
        float bzR = skipP ? n2.z : NEGV, wzR = skipP ? n2.w : 0.f;           \
        float mRP, sP;  LAE(mR1, sR1, bzR, wzR, mRP, sP);                    \
        float bP = __fadd_rn(mRP, (e1p));                                    \
        float mA, sA; LAE(be, se, n1.z, n1.w, mA, sA);                       \
        float m1, s1; LAE(bo, so, be, se, m1, s1);                           \
        float bzB = skip ? n1.z : NEGV, wzB = skip ? n1.w : 0.f;             \
        float mC, sC; LAE(m1, s1, bzB, wzB, mC, sC);                         \
        float be1 = __fadd_rn(mA, (e1b)), se1 = sA;                          \
        float bo1 = __fadd_rn(mC, (e1o)), so1 = sC;                          \
        float mD, sD; LAE(be1, se1, bP, sP, mD, sD);                         \
        float mE, sE; LAE(bo1, so1, be1, se1, mE, sE);                       \
        float bzF = skip ? bP : NEGV, wzF = skip ? sP : 0.f;                 \
        float mF, sF; LAE(mE, sE, bzF, wzF, mF, sF);                         \
        be = __fadd_rn(mD, (e2b)); se = sD;                                  \
        bo = __fadd_rn(mF, (e2o)); so = sF;                                  \
    }

    int ts = 0;
    if (last & 1) {                      // one plain step so pairs align
        float4 n1 = sh[buf][i + 1];
        const float* p = em + EP;        // t = 1
        float e_b = p[0];
        float e_o = p[jo];
        float mA, sA; LAE(be, se, n1.z, n1.w, mA, sA);
        float m1, s1; LAE(bo, so, be, se, m1, s1);
        float bz = skip ? n1.z : NEGV, wz = skip ? n1.w : 0.f;
        float mC, sC; LAE(m1, s1, bz, wz, mC, sC);
        be = __fadd_rn(mA, e_b); se = sA;
        bo = __fadd_rn(mC, e_o); so = sC;
        ts = 1;
        buf ^= 1;
        sh[buf][i + 2] = make_float4(be, se, bo, so);
        __syncthreads();
    }
    const int npairs = (last - ts) >> 1;
    const int nmain  = npairs & ~(DP - 1);

    // Register prefetch rings (literal indices only).
    float r1b[DP], r1o[DP], r1p[DP], r2b[DP], r2o[DP];
#pragma unroll
    for (int k = 0; k < DP; ++k) {
        const float* p1 = em + (size_t)(ts + 2 * k + 1) * EP;
        r1b[k] = p1[0];  r1o[k] = p1[jo];      r1p[k] = p1[jp];
        r2b[k] = p1[EP]; r2o[k] = p1[EP + jo];
    }

    for (int pg = 0; pg < nmain; pg += DP) {
        // Confirm the pipelined chunk (value issued a full group ago).
        if (pfc >= 0) {
            if (pfv == 0)
                while (ld_acq(&g_flag[pfc * Bb + b]) == 0) {}
            nextc = pfc;
            pfc = (nextc < maxc) ? nextc + 1 : -1;
            if (pfc >= 0) pfv = ld_acq(&g_flag[pfc * Bb + b]);
        }
#pragma unroll
        for (int k = 0; k < DP; ++k) {
            const int p = pg + k;
            const float e1b = r1b[k], e1o = r1o[k], e1p = r1p[k];
            const float e2b = r2b[k], e2o = r2o[k];
            int q = p + DP; if (q >= npairs) q = npairs - 1;
            const float* pp1 = em + (size_t)(ts + 2 * q + 1) * EP;
            r1b[k] = pp1[0];  r1o[k] = pp1[jo];      r1p[k] = pp1[jp];
            r2b[k] = pp1[EP]; r2o[k] = pp1[EP + jo];

            PAIR_BODY(e1b, e1o, e1p, e2b, e2o);

            if ((p & 15) == 15) {        // fold every 32 steps
                be = fmaxf(be + lg2f(se), NEGV); se = 1.f;
                bo = fmaxf(bo + lg2f(so), NEGV); so = 1.f;
            }
            buf ^= 1;
            sh[buf][i + 2] = make_float4(be, se, bo, so);
            __syncthreads();
        }
    }

    // Safety: confirm any chunks not yet verified (normally a no-op).
    for (int c = nextc + 1; c <= maxc; ++c)
        while (ld_acq(&g_flag[c * Bb + b]) == 0) {}

    // Remainder pairs (<=3): ring-free.
    for (int p = nmain; p < npairs; ++p) {
        const float* p1 = em + (size_t)(ts + 2 * p + 1) * EP;
        float e1b = p1[0],  e1o = p1[jo], e1p = p1[jp];
        float e2b = p1[EP], e2o = p1[EP + jo];
        PAIR_BODY(e1b, e1o, e1p, e2b, e2o);
        buf ^= 1;
        sh[buf][i + 2] = make_float4(be, se, bo, so);
        __syncthreads();
    }

    // Final fold + publish.
    be = fmaxf(be + lg2f(se), NEGV);
    bo = fmaxf(bo + lg2f(so), NEGV);
    buf ^= 1;
    sh[buf][i + 2] = make_float4(be, 1.f, bo, 1.f);
    __syncthreads();

    if (i == 0) {
        int Lb = tlen[b];
        float x = sh[buf][Lb + 2].x;     // even state 2Lb
        float y = sh[buf][Lb + 1].z;     // odd  state 2Lb-1
        float m = fmaxf(x, y);
        g_tot[b] = LN2 * (m + lg2f(ex2f(x - m) + ex2f(y - m)));
        __threadfence();
        unsigned v = atomicAdd(&g_done, 1u);
        s_lastflag = (v == Bb - 1u) ? 1 : 0;
    }
    __syncthreads();

    if (s_lastflag && i < 32) {          // last alpha block: fused reduction
        __threadfence();
        float tot = g_tot[i];
        float il  = (float)ilen[i];
        bool  ok  = tot > NEGV * 0.5f;
        float tsum = ok ? tot : 0.f;
        float tf   = ok ? il  : 0.f;
        float af   = il;
#pragma unroll
        for (int s = 16; s >= 1; s >>= 1) {
            tsum += __shfl_down_sync(0xFFFFFFFFu, tsum, s);
            tf   += __shfl_down_sync(0xFFFFFFFFu, tf, s);
            af   += __shfl_down_sync(0xFFFFFFFFu, af, s);
        }
        if (i == 0) {
            out[0] = tsum; out[1] = tf; out[2] = af;
            g_done = 0;
        }
    }
}

// ---------------------------------------------------------------------------
extern "C" void kernel_launch(void* const* d_in, const int* in_sizes, int n_in,
                              void* d_out, int out_size) {
    const float* lp      = (const float*)d_in[0];  // nnet_output [B,T,C] f32
    const int*   targets = (const int*)  d_in[1];  // [B,L] i32
    const int*   ilen    = (const int*)  d_in[2];  // [B] i32
    const int*   tlen    = (const int*)  d_in[3];  // [B] i32

    static bool attr_set = false;
    if (!attr_set) {
        cudaFuncSetAttribute(ctc_main,
                             cudaFuncAttributeMaxDynamicSharedMemorySize,
                             SMEM_DYN);
        attr_set = true;
    }

    reset_kernel<<<(NGATHER + 255) / 256, 256>>>();
    ctc_main<<<Bb + NGATHER, NTHR, SMEM_DYN>>>(lp, targets, ilen, tlen,
                                               (float*)d_out);
}

// round 15
// speedup vs baseline: 1.4957x; 1.4957x over previous
#include <cuda_runtime.h>
#include <cstddef>
#include <cstdint>

// CTC loss forward. B=32, T=800, C=5000, L=100, S=201.
//
// R14: R11's serial split (gather at its 36us DRAM floor; overlap attempts
// R12/R13 abandoned) + a rebuilt alpha:
//   * 4 warps x 32 lanes x 2 states, slot = 26w-6+l; lanes 0-5 are a
//     redundant halo, lanes 6-31 are outputs (104 slots >= 101).
//   * 6-step windows: inside a window the only exchange is 2 shfl_up/step --
//     NO smem, NO barriers. One __syncthreads + renorm + double-buffered
//     publish/reload per 6 steps. (R8's proven-correct halo algorithm, minus
//     its local-memory pathology: rings indexed ONLY by literals inside a
//     fully unrolled window; remainder steps use direct loads.)
//   * emissions from the dense emit scratch (coalesced, L2-resident).

#define Bb 32
#define Tt 800
#define Cc 5000
#define Ll 100
#define EP 128            // emit row stride (floats), line-aligned
#define NEGV (-1e30f)
#define LOG2E 1.4426950408889634f
#define LN2   0.6931471805599453f
#define W 6               // window length == halo depth == ring depth
#define NTHR 128

__device__ float    g_emit[(size_t)Bb * Tt * EP];
__device__ float    g_tot[Bb];
__device__ unsigned g_done;          // self-resetting

__device__ __forceinline__ float ex2f(float x) {
    float y; asm("ex2.approx.ftz.f32 %0, %1;" : "=f"(y) : "f"(x)); return y;
}
__device__ __forceinline__ float lg2f(float x) {
    float y; asm("lg2.approx.ftz.f32 %0, %1;" : "=f"(y) : "f"(x)); return y;
}

// (base,sum) logaddexp combine: (bx,sx) (+) (by,sy) -> (mb, ms), single ex2.
#define LAE(bx, sx, by, sy, mb, ms)                                        \
    {                                                                      \
        float d_ = __fadd_rn(bx, -(by));                                   \
        float u_ = ex2f(fminf(d_, -d_));                                   \
        mb = fmaxf(bx, by);                                                \
        ms = (d_ >= 0.f) ? __fmaf_rn(sy, u_, sx) : __fmaf_rn(sx, u_, sy);  \
    }

// One CTC time step. Reads neighbor's odd (base,sum) via shfl; lane 0
// self-clamps (garbage contained in the halo).
#define STEP(ecb, eco)                                                     \
    {                                                                      \
        float nbz = __shfl_up_sync(0xffffffffu, bo, 1);                    \
        float nbw = __shfl_up_sync(0xffffffffu, so, 1);                    \
        float mA, sA; LAE(be, se, nbz, nbw, mA, sA);                       \
        float m1, s1; LAE(bo, so, be, se, m1, s1);                         \
        float bz = skip ? nbz : NEGV, wz = skip ? nbw : 0.f;               \
        float mC, sC; LAE(m1, s1, bz, wz, mC, sC);                         \
        be = __fadd_rn(mA, (ecb)); se = sA;                                \
        bo = __fadd_rn(mC, (eco)); so = sC;                                \
    }

// ---------------------------------------------------------------------------
// Kernel 1: gather (full chip). emit[bt][j] = LOG2E * lp[bt, col(j)].
// ---------------------------------------------------------------------------
__global__ void gather_kernel(const float* __restrict__ lp,
                              const int* __restrict__ targets,
                              const int* __restrict__ ilen) {
    int idx = blockIdx.x * blockDim.x + threadIdx.x;
    const int total = Bb * Tt * (Ll + 1);
    if (idx >= total) return;
    int j  = idx % (Ll + 1);
    int bt = idx / (Ll + 1);
    int b  = bt / Tt;
    int t  = bt - b * Tt;
    if (t >= ilen[b]) return;
    int c = (j == 0) ? 0 : targets[b * Ll + (j - 1)];
    g_emit[(size_t)bt * EP + j] = LOG2E * __ldg(lp + (size_t)bt * Cc + c);
}

// ---------------------------------------------------------------------------
// Kernel 2: shfl-windowed alpha + fused reduction. grid=B, 128 threads.
// ---------------------------------------------------------------------------
__global__ __launch_bounds__(NTHR, 1)
void ctc_alpha(const int* __restrict__ targets,
               const int* __restrict__ ilen,
               const int* __restrict__ tlen,
               float* __restrict__ out)
{
    // pub[buf][slot+6]; indices 0..5 are permanent left-boundary pads.
    __shared__ float4 pub[2][110];
    __shared__ int s_lastflag;

    const int b = blockIdx.x;
    const int i = threadIdx.x;
    const int w = i >> 5;
    const int l = i & 31;
    const int slot = 26 * w - 6 + l;     // -6 .. 103
    const int last = ilen[b] - 1;        // >= 599 for this problem

    const int tgR  = (slot >= 0 && slot < Ll)  ? targets[b * Ll + slot]     : 0;
    const int tgpR = (slot >= 1 && slot <= Ll) ? targets[b * Ll + slot - 1] : -1;
    const bool skip = (tgR != tgpR);
    const int jo = (slot >= 0 && slot < Ll) ? slot + 1 : 0;  // odd emission col

    const float* __restrict__ em = g_emit + (size_t)b * Tt * EP;

    if (i < W) {                         // left pads, both buffers, once
        pub[0][i] = make_float4(NEGV, 1.f, NEGV, 1.f);
        pub[1][i] = make_float4(NEGV, 1.f, NEGV, 1.f);
    }

    // t=0 init (log2 domain, alpha = base + lg2(sum)); only slot 0 live.
    float se = 1.f, so = 1.f;
    float be = (slot == 0) ? em[0]  : NEGV;
    float bo = (slot == 0) ? em[jo] : NEGV;

    __syncthreads();                     // pads visible before first reload

    // Prefetch ring for window 0 (steps 1..W), literal indices only.
    float eb[W], eo[W];
#pragma unroll
    for (int k = 0; k < W; ++k) {
        int tt = 1 + k; if (tt > last) tt = last;
        eb[k] = em[(size_t)tt * EP];
        eo[k] = em[(size_t)tt * EP + jo];
    }

    const int nwin = last / W;           // full windows (steps 1..nwin*W)
    int buf = 0;

    for (int n = 0; n < nwin; ++n) {
        const int tnext = n * W + W;     // first step of the NEXT window
#pragma unroll
        for (int u = 0; u < W; ++u) {    // u literal -> rings in registers
            const float ecb = eb[u], eco = eo[u];
            int q = tnext + u + 1; if (q > last) q = last;
            eb[u] = em[(size_t)q * EP];
            eo[u] = em[(size_t)q * EP + jo];
            STEP(ecb, eco);
        }
        // Window boundary: renorm (3^6 growth, safe), publish, reload halo.
        be = fmaxf(be + lg2f(se), NEGV); se = 1.f;
        bo = fmaxf(bo + lg2f(so), NEGV); so = 1.f;
        buf ^= 1;
        if (l >= W) pub[buf][slot + 6] = make_float4(be, 1.f, bo, 1.f);
        __syncthreads();
        if (l < W) {
            float4 v = pub[buf][slot + 6];
            be = v.x; se = v.y; bo = v.z; so = v.w;
        }
    }

    // Remainder steps (<= W-1): direct loads, shfl only; contamination
    // depth <= 5 stays inside the 6-lane halo.
    for (int t = nwin * W + 1; t <= last; ++t) {
        const float ecb = em[(size_t)t * EP];
        const float eco = em[(size_t)t * EP + jo];
        STEP(ecb, eco);
    }

    // Final fold + publish output lanes.
    be = fmaxf(be + lg2f(se), NEGV);
    bo = fmaxf(bo + lg2f(so), NEGV);
    buf ^= 1;
    if (l >= W) pub[buf][slot + 6] = make_float4(be, 1.f, bo, 1.f);
    __syncthreads();

    if (i == 0) {
        int Lb = tlen[b];
        float x = pub[buf][Lb + 6].x;        // even state 2Lb   (slot Lb)
        float y = pub[buf][Lb - 1 + 6].z;    // odd  state 2Lb-1 (slot Lb-1)
        float m = fmaxf(x, y);
        g_tot[b] = LN2 * (m + lg2f(ex2f(x - m) + ex2f(y - m)));
        __threadfence();
        unsigned v = atomicAdd(&g_done, 1u);
        s_lastflag = (v == Bb - 1u) ? 1 : 0;
    }
    __syncthreads();

    if (s_lastflag && i < 32) {              // last block: fused reduction
        __threadfence();
        float tot = g_tot[i];
        float il  = (float)ilen[i];
        bool  ok  = tot > NEGV * 0.5f;
        float tsum = ok ? tot : 0.f;
        float tf   = ok ? il  : 0.f;
        float af   = il;
#pragma unroll
        for (int s = 16; s >= 1; s >>= 1) {
            tsum += __shfl_down_sync(0xFFFFFFFFu, tsum, s);
            tf   += __shfl_down_sync(0xFFFFFFFFu, tf, s);
            af   += __shfl_down_sync(0xFFFFFFFFu, af, s);
        }
        if (i == 0) {
            out[0] = tsum; out[1] = tf; out[2] = af;
            g_done = 0;                      // reset for next graph replay
        }
    }
}

// ---------------------------------------------------------------------------
extern "C" void kernel_launch(void* const* d_in, const int* in_sizes, int n_in,
                              void* d_out, int out_size) {
    const float* lp      = (const float*)d_in[0];  // nnet_output [B,T,C] f32
    const int*   targets = (const int*)  d_in[1];  // [B,L] i32
    const int*   ilen    = (const int*)  d_in[2];  // [B] i32
    const int*   tlen    = (const int*)  d_in[3];  // [B] i32

    const int total = Bb * Tt * (Ll + 1);
    gather_kernel<<<(total + 255) / 256, 256>>>(lp, targets, ilen);
    ctc_alpha<<<Bb, NTHR>>>(targets, ilen, tlen, (float*)d_out);
}